// round 1
// baseline (speedup 1.0000x reference)
#include <cuda_runtime.h>
#include <math.h>

#define THREADS 256
#define NBLOCKS 1184            // 148 SMs * 8 CTAs
#define ROWS_PER_CHUNK 256      // one row per thread per chunk
#define ERR_OK 0.1f

__device__ float g_partials[NBLOCKS];

__global__ __launch_bounds__(THREADS)
void loss_partial_kernel(const float* __restrict__ in,
                         const float* __restrict__ tg,
                         int n)
{
    __shared__ float s_in[ROWS_PER_CHUNK * 5];   // 5 KB
    const int t = threadIdx.x;

    float acc = 0.0f;

    const int stride_rows = gridDim.x * ROWS_PER_CHUNK;
    for (int base = blockIdx.x * ROWS_PER_CHUNK; base < n; base += stride_rows) {
        const int rows = min(ROWS_PER_CHUNK, n - base);
        const int nflt = rows * 5;
        const int flat = base * 5;   // max 100M < 2^31, int OK

        __syncthreads();   // protect smem from previous iteration's readers
        #pragma unroll
        for (int i = t; i < ROWS_PER_CHUNK * 5; i += THREADS) {
            if (i < nflt) s_in[i] = in[flat + i];   // fully coalesced
        }
        __syncthreads();

        if (t < rows) {
            // stride-5 smem reads: 5 coprime with 32 banks -> conflict-free
            const float x0 = s_in[5 * t + 0];
            const float x2 = s_in[5 * t + 2];
            const float x4 = s_in[5 * t + 4];
            const float tv = tg[base + t];          // coalesced
            const float d = (fabsf(x4 - x2) < ERR_OK) ? (x0 - x4) : (x0 - tv);
            acc += fabsf(d);
        }
    }

    // ---- block reduction (deterministic) ----
    __shared__ float red[THREADS];
    red[t] = acc;
    __syncthreads();
    #pragma unroll
    for (int s = THREADS / 2; s >= 32; s >>= 1) {
        if (t < s) red[t] += red[t + s];
        __syncthreads();
    }
    if (t < 32) {
        float v = red[t];
        #pragma unroll
        for (int off = 16; off > 0; off >>= 1)
            v += __shfl_down_sync(0xFFFFFFFFu, v, off);
        if (t == 0) g_partials[blockIdx.x] = v;
    }
}

__global__ __launch_bounds__(THREADS)
void loss_final_kernel(float* __restrict__ out, int n)
{
    __shared__ double sd[THREADS];
    const int t = threadIdx.x;
    double s = 0.0;
    for (int i = t; i < NBLOCKS; i += THREADS)
        s += (double)g_partials[i];
    sd[t] = s;
    __syncthreads();
    #pragma unroll
    for (int st = THREADS / 2; st > 0; st >>= 1) {
        if (t < st) sd[t] += sd[t + st];
        __syncthreads();
    }
    if (t == 0) out[0] = (float)(sd[0] / (double)n);
}

extern "C" void kernel_launch(void* const* d_in, const int* in_sizes, int n_in,
                              void* d_out, int out_size)
{
    const float* inputs  = (const float*)d_in[0];   // [N, 5] float32
    const float* targets = (const float*)d_in[1];   // [N, 1] float32
    float* out = (float*)d_out;

    const int n = in_sizes[1];   // N rows (targets has N elements)

    loss_partial_kernel<<<NBLOCKS, THREADS>>>(inputs, targets, n);
    loss_final_kernel<<<1, THREADS>>>(out, n);
}

// round 2
// speedup vs baseline: 1.3172x; 1.3172x over previous
#include <cuda_runtime.h>
#include <math.h>

#define THREADS 256
#define NBLOCKS 1184            // 148 SMs * 8 CTAs, persistent grid-stride
#define ROWS 1024               // rows per block per chunk (20KB smem)
#define ERR_OK 0.1f

__device__ float g_partials[NBLOCKS];
__device__ unsigned int g_count = 0;

__global__ __launch_bounds__(THREADS)
void loss_fused_kernel(const float* __restrict__ in,
                       const float* __restrict__ tg,
                       float* __restrict__ out,
                       int n)
{
    __shared__ float4 s4[ROWS * 5 / 4];      // 1280 float4 = 20 KB
    const int t = threadIdx.x;

    float acc = 0.0f;

    const long long stride_rows = (long long)gridDim.x * ROWS;
    for (long long base = (long long)blockIdx.x * ROWS; base < n; base += stride_rows) {
        const int rows = (int)min((long long)ROWS, (long long)n - base);

        __syncthreads();   // protect smem from previous iteration's readers

        if (rows == ROWS) {
            // ---- fast path: fully vectorized ----
            const float4* g4 = (const float4*)(in + base * 5);  // 16B aligned (base mult of 1024)
            #pragma unroll
            for (int k = 0; k < 5; k++)
                s4[t + k * THREADS] = g4[t + k * THREADS];      // coalesced LDG.128 + STS.128
            const float4 tv = ((const float4*)(tg + base))[t];  // coalesced LDG.128
            __syncthreads();

            // Thread t owns rows 4t..4t+3 = floats [20t, 20t+20).
            // 5x LDS.128, stride 20 floats across lanes -> conflict-free.
            const float4 a0 = s4[5 * t + 0];
            const float4 a1 = s4[5 * t + 1];
            const float4 a2 = s4[5 * t + 2];
            const float4 a3 = s4[5 * t + 3];
            const float4 a4 = s4[5 * t + 4];

            // row 0: x0=a0.x x2=a0.z x4=a1.x
            const float d0 = (fabsf(a1.x - a0.z) < ERR_OK) ? (a0.x - a1.x) : (a0.x - tv.x);
            // row 1: x0=a1.y x2=a1.w x4=a2.y
            const float d1 = (fabsf(a2.y - a1.w) < ERR_OK) ? (a1.y - a2.y) : (a1.y - tv.y);
            // row 2: x0=a2.z x2=a3.x x4=a3.z
            const float d2 = (fabsf(a3.z - a3.x) < ERR_OK) ? (a2.z - a3.z) : (a2.z - tv.z);
            // row 3: x0=a3.w x2=a4.y x4=a4.w
            const float d3 = (fabsf(a4.w - a4.y) < ERR_OK) ? (a3.w - a4.w) : (a3.w - tv.w);

            acc += fabsf(d0) + fabsf(d1) + fabsf(d2) + fabsf(d3);
        } else {
            // ---- tail path: scalar (runs at most once, on <1024 rows) ----
            float* s = (float*)s4;
            const int nflt = rows * 5;
            for (int i = t; i < nflt; i += THREADS)
                s[i] = in[base * 5 + i];
            __syncthreads();
            for (int r = t; r < rows; r += THREADS) {
                const float x0 = s[5 * r + 0];
                const float x2 = s[5 * r + 2];
                const float x4 = s[5 * r + 4];
                const float tvv = tg[base + r];
                const float d = (fabsf(x4 - x2) < ERR_OK) ? (x0 - x4) : (x0 - tvv);
                acc += fabsf(d);
            }
        }
    }

    // ---- deterministic block reduction ----
    __shared__ float red[THREADS];
    __syncthreads();
    red[t] = acc;
    __syncthreads();
    #pragma unroll
    for (int s = THREADS / 2; s >= 32; s >>= 1) {
        if (t < s) red[t] += red[t + s];
        __syncthreads();
    }
    if (t < 32) {
        float v = red[t];
        #pragma unroll
        for (int off = 16; off > 0; off >>= 1)
            v += __shfl_down_sync(0xFFFFFFFFu, v, off);
        if (t == 0) g_partials[blockIdx.x] = v;
    }

    // ---- fused final reduction: last block to finish sums all partials ----
    __shared__ bool is_last;
    __threadfence();                      // release: make partial visible
    if (t == 0) {
        const unsigned int c = atomicAdd(&g_count, 1u);
        is_last = (c == gridDim.x - 1);
    }
    __syncthreads();

    if (is_last) {
        __threadfence();                  // acquire: see all partials
        double s = 0.0;
        for (int i = t; i < (int)gridDim.x; i += THREADS)
            s += (double)g_partials[i];
        __shared__ double sd[THREADS];
        sd[t] = s;
        __syncthreads();
        #pragma unroll
        for (int st = THREADS / 2; st > 0; st >>= 1) {
            if (t < st) sd[t] += sd[t + st];
            __syncthreads();
        }
        if (t == 0) {
            out[0] = (float)(sd[0] / (double)n);
            g_count = 0;                  // reset for next graph replay
        }
    }
}

extern "C" void kernel_launch(void* const* d_in, const int* in_sizes, int n_in,
                              void* d_out, int out_size)
{
    const float* inputs  = (const float*)d_in[0];   // [N, 5] float32
    const float* targets = (const float*)d_in[1];   // [N, 1] float32
    float* out = (float*)d_out;

    const int n = in_sizes[1];   // N rows (targets has N elements)

    loss_fused_kernel<<<NBLOCKS, THREADS>>>(inputs, targets, out, n);
}